// round 17
// baseline (speedup 1.0000x reference)
#include <cuda_runtime.h>
#include <cuda_fp16.h>

#define BATCH   8192
#define HID     128
#define TT      12
#define LAYERS  10
#define G4      512
#define ENCL    4096
#define NMODES  25

// chunks: layer0 = 8 + 11*8 = 96 (Gx cached), layers 1..9 = 8 + 11*16 = 184
#define NCHUNK_TOTAL (96 + 9 * 184)   // 1752

// ---------------- scratch (static device globals; no allocation) ----------------
__device__ __half g_encp[BATCH * HID];
__device__ __half g_Xa  [TT * BATCH * HID];
__device__ __half g_Xb  [TT * BATCH * HID];
__device__ __half g_Wp  [LAYERS * 16 * 16 * 512];
__device__ float  g_Gx  [BATCH * G4];          // layer-0 x-part gate cache
__device__ float  g_plog[BATCH * NMODES];

// ---------------- helpers ----------------
__device__ __forceinline__ void mma_f16(float c[4],
                                        unsigned a0, unsigned a1, unsigned a2, unsigned a3,
                                        unsigned b0, unsigned b1) {
    asm volatile(
        "mma.sync.aligned.m16n8k16.row.col.f32.f16.f16.f32 "
        "{%0,%1,%2,%3}, {%4,%5,%6,%7}, {%8,%9}, {%0,%1,%2,%3};\n"
        : "+f"(c[0]), "+f"(c[1]), "+f"(c[2]), "+f"(c[3])
        : "r"(a0), "r"(a1), "r"(a2), "r"(a3), "r"(b0), "r"(b1));
}
__device__ __forceinline__ float sigf(float x) { return __fdividef(1.f, 1.f + __expf(-x)); }
__device__ __forceinline__ float tanh_fast(float x) { return __fdividef(2.f, 1.f + __expf(-2.f * x)) - 1.f; }

__device__ __forceinline__ void cp16(void* dst_smem, const void* src) {
    unsigned d = (unsigned)__cvta_generic_to_shared(dst_smem);
    asm volatile("cp.async.cg.shared.global [%0], [%1], 16;\n" :: "r"(d), "l"(src));
}
#define CP_COMMIT() asm volatile("cp.async.commit_group;\n" ::: "memory")
#define CP_WAIT(N)  asm volatile("cp.async.wait_group %0;\n" :: "n"(N) : "memory")

// fragment-packed fp16 X/H tile (64r x 128c): one LDS.128 = full mma A fragment
__device__ __forceinline__ int xpack_off(int r6, int col) {
    int c = col >> 4, t4 = (col >> 1) & 3, kh = (col >> 3) & 1, d = col & 1;
    int mf = r6 >> 4, q = (r6 >> 3) & 1, g = r6 & 7;
    return c * 1024 + mf * 256 + (g * 4 + t4) * 8 + kh * 4 + q * 2 + d;
}

// ---------------- weight pre-pack ----------------
__global__ void __launch_bounds__(256) k_pack(const float* __restrict__ Wih,
                                              const float* __restrict__ Whh,
                                              __half* __restrict__ Wp) {
    int idx = blockIdx.x * 256 + threadIdx.x;
    if (idx >= LAYERS * 16 * 16 * 512) return;
    int hoff = idx & 511;
    int w    = (idx >> 9) & 15;
    int kc   = (idx >> 13) & 15;
    int l    = idx >> 17;
    int gidx = hoff >> 4, rem = hoff & 15;
    int g = gidx >> 2, t4 = gidx & 3;
    int P = (rem >> 3) ^ (g & 1);
    int gt = P * 2 + ((rem >> 2) & 1);
    int kh = (rem >> 1) & 1, d = rem & 1;
    int col = gt * 128 + w * 8 + g;
    int kk  = (kc & 7) * 16 + kh * 8 + t4 * 2 + d;
    float v = (kc < 8) ? Wih[((size_t)l * 512 + col) * 128 + kk]
                       : Whh[((size_t)l * 512 + col) * 128 + kk];
    Wp[idx] = __float2half_rn(v);
}

// ---------------- fc_in: fp16 core, LDG->cvt->STS 3-stage pipeline ----------------
__global__ void __launch_bounds__(256) k_fcin(const float* __restrict__ A,
                                              const float* __restrict__ W,
                                              const float* __restrict__ bias,
                                              __half* __restrict__ out) {
    __shared__ __align__(16) __half sA[3][2048];   // 64r x 32k frag-packed per stage
    __shared__ __align__(16) __half sB[3][4096];   // [kk][n][16k] per stage
    const int tid  = threadIdx.x;
    const int lane = tid & 31;
    const int w    = tid >> 5;
    const int wm   = w & 3;
    const int wn   = w >> 2;
    const int row0 = blockIdx.x * 64;
    const int g    = lane >> 2;
    const int t4   = lane & 3;
    const int gidx = g * 4 + t4;

    const int ar = tid >> 2, aks = tid & 3;
    const int bn = tid >> 1, bh = tid & 1;
    const int abase = (aks >> 1) * 1024 + (ar >> 4) * 256 + (ar & 7) * 32
                    + (aks & 1) * 4 + ((ar >> 3) & 1) * 2;

    float a_r[8], b_r[16];
    auto ldg = [&](int s) {
        int ka = s * 32 + aks * 8;
        *(float4*)&a_r[0] = *(const float4*)(A + (size_t)(row0 + ar) * ENCL + ka);
        *(float4*)&a_r[4] = *(const float4*)(A + (size_t)(row0 + ar) * ENCL + ka + 4);
        int kb = s * 32 + bh * 16;
#pragma unroll
        for (int i = 0; i < 4; i++)
            *(float4*)&b_r[i * 4] = *(const float4*)(W + (size_t)bn * ENCL + kb + i * 4);
    };
    auto sts = [&](int s) {
        __half* dA = sA[s % 3] + abase;
#pragma unroll
        for (int i = 0; i < 4; i++)
            *(__half2*)&dA[i * 8] = __floats2half2_rn(a_r[i * 2], a_r[i * 2 + 1]);
        __half2 tb[8];
#pragma unroll
        for (int i = 0; i < 8; i++) tb[i] = __floats2half2_rn(b_r[i * 2], b_r[i * 2 + 1]);
        __half* dB = sB[s % 3] + bh * 2048 + bn * 16;
        *(uint4*)&dB[0] = *(uint4*)&tb[0];
        *(uint4*)&dB[8] = *(uint4*)&tb[4];
    };

    float acc[8][4];
#pragma unroll
    for (int i = 0; i < 8; i++)
#pragma unroll
        for (int j = 0; j < 4; j++) acc[i][j] = 0.f;

    ldg(0); sts(0); ldg(1);
    __syncthreads();

    const int S = ENCL / 32;   // 128
    for (int s = 0; s < S; s++) {
        if (s + 1 < S) sts(s + 1);
        if (s + 2 < S) ldg(s + 2);
        const __half* cA = sA[s % 3];
        const __half* cB = sB[s % 3];
#pragma unroll
        for (int kk = 0; kk < 2; kk++) {
            uint4 Af = *(const uint4*)&cA[kk * 1024 + wm * 256 + gidx * 8];
#pragma unroll
            for (int nf = 0; nf < 8; nf++) {
                int col = wn * 64 + nf * 8 + g;
                unsigned b0 = *(const unsigned*)&cB[kk * 2048 + col * 16 + t4 * 2];
                unsigned b1 = *(const unsigned*)&cB[kk * 2048 + col * 16 + 8 + t4 * 2];
                mma_f16(acc[nf], Af.x, Af.y, Af.z, Af.w, b0, b1);
            }
        }
        __syncthreads();
    }
#pragma unroll
    for (int nf = 0; nf < 8; nf++)
#pragma unroll
        for (int cr = 0; cr < 4; cr++) {
            int r   = row0 + wm * 16 + g + (cr >> 1) * 8;
            int col = wn * 64 + nf * 8 + t4 * 2 + (cr & 1);
            float v = fmaxf(acc[nf][cr] + bias[col], 0.f);
            out[(size_t)(r & ~63) * 128 + xpack_off(r & 63, col)] = __float2half_rn(v);
        }
}

// ---------------- persistent fused LSTM ----------------
#define OFFB_XS   65536
#define OFFB_HS   98304
#define OFFB_BIAS 114688
#define SMEM_BYTES (114688 + 2048)

__global__ void __launch_bounds__(512, 1) k_lstm(const __half* __restrict__ enc,
                                                 const __half* __restrict__ Wp,
                                                 const float* __restrict__ bih,
                                                 const float* __restrict__ bhh,
                                                 __half* __restrict__ Xa,
                                                 __half* __restrict__ Xb,
                                                 float* __restrict__ Gx) {
    extern __shared__ __align__(16) unsigned char smraw[];
    __half* Bsh = (__half*)smraw;
    __half* Xsb = (__half*)(smraw + OFFB_XS);
    __half* Hs  = (__half*)(smraw + OFFB_HS);
    float*  bs  = (float*)(smraw + OFFB_BIAS);

    const int tid  = threadIdx.x;
    const int lane = tid & 31;
    const int w    = tid >> 5;
    const int g    = lane >> 2;
    const int t4   = lane & 3;
    const int gidx = g * 4 + t4;
    const int gsw  = g & 1;
    const int row0 = blockIdx.x * 64;
    __half* Bw = Bsh + w * 2048;

    float creg[16];
#pragma unroll
    for (int i = 0; i < 16; i++) creg[i] = 0.f;

    bs[tid] = bih[tid] + bhh[tid];
#pragma unroll
    for (int i = 0; i < 2; i++) {
        int idx = i * 512 + tid;
        *(uint4*)&Xsb[idx * 8] = *(const uint4*)&enc[(size_t)row0 * 128 + idx * 8];
    }
    __syncthreads();

    auto issueB = [&](int nn) {
        int lq, kcq;
        if (nn < 96) { lq = 0; kcq = (nn < 8) ? nn : 8 + ((nn - 8) & 7); }
        else {
            int m2 = nn - 96;
            lq = 1 + m2 / 184;
            int rq = m2 % 184;
            kcq = (rq < 8) ? rq : ((rq - 8) & 15);
        }
        const __half* src = Wp + (((size_t)(lq * 16 + kcq) * 16 + w) << 9);
        __half* dst = Bw + (nn & 3) * 512;
        cp16(dst + lane * 8, src + lane * 8);
        cp16(dst + 256 + lane * 8, src + 256 + lane * 8);
    };
    auto issueX = [&](const __half* srcT, int xb) {
#pragma unroll
        for (int i = 0; i < 2; i++) {
            int off = w * 512 + i * 256 + lane * 8;
            cp16(Xsb + xb * 8192 + off, srcT + (size_t)row0 * 128 + off);
        }
    };

    issueB(0); CP_COMMIT();
    issueB(1); CP_COMMIT();
    issueB(2); CP_COMMIT();

    const __half* Xin = Xa;
    __half*       Xout = Xa;
    float acc[4][4][4];
    int n = 0;
    int xbuf = 0;

    for (int l = 0; l < LAYERS; l++) {
        for (int t = 0; t < TT; t++) {
            const bool isL0x = (l == 0 && t > 0);
            const int  nkc   = (l == 0 || t == 0) ? 8 : 16;
            const int  hsync = isL0x ? 0 : 8;
            const int  trig  = (nkc == 8) ? 3 : 7;
            const bool needX = (t < TT - 1) ? (l > 0) : (l < LAYERS - 1);
            const __half* xsrc = (t < TT - 1) ? (Xin + (size_t)(t + 1) * BATCH * 128) : Xout;

            if (isL0x) {   // reload layer-0 x-part gates
                const uint4* gp = (const uint4*)(Gx + (size_t)row0 * 512 + (size_t)tid * 64);
                uint4* ap = (uint4*)acc;
#pragma unroll
                for (int i = 0; i < 16; i++) ap[i] = gp[i];
            } else {
#pragma unroll
                for (int a = 0; a < 4; a++)
#pragma unroll
                    for (int b = 0; b < 4; b++)
#pragma unroll
                        for (int q = 0; q < 4; q++) acc[a][b][q] = 0.f;
            }

            for (int kc = 0; kc < nkc; kc++) {
                if (kc == hsync) __syncthreads();    // prev epilogue's Hs visible
                CP_WAIT(2);
                const __half* Bb = Bw + (n & 3) * 512;
                const __half* Asrc;
                if (l == 0) Asrc = (t == 0) ? (Xsb + kc * 1024) : (Hs + kc * 1024);
                else        Asrc = (kc < 8) ? (Xsb + xbuf * 8192 + kc * 1024)
                                            : (Hs + (kc - 8) * 1024);
                uint4 Af[4];
#pragma unroll
                for (int mf = 0; mf < 4; mf++)
                    Af[mf] = *(const uint4*)&Asrc[mf * 256 + gidx * 8];
                unsigned b0[4], b1[4];
#pragma unroll
                for (int P = 0; P < 2; P++) {
                    uint4 Bv = *(const uint4*)&Bb[gidx * 16 + (P ^ gsw) * 8];
                    b0[P * 2] = Bv.x;  b1[P * 2] = Bv.y;
                    b0[P * 2 + 1] = Bv.z;  b1[P * 2 + 1] = Bv.w;
                }
#pragma unroll
                for (int gt = 0; gt < 4; gt++)
#pragma unroll
                    for (int mf = 0; mf < 4; mf++)
                        mma_f16(acc[mf][gt], Af[mf].x, Af[mf].y, Af[mf].z, Af[mf].w,
                                b0[gt], b1[gt]);

                if (kc == trig && needX) { issueX(xsrc, xbuf ^ 1); CP_COMMIT(); }
                int gn = n + 3;
                if (gn < NCHUNK_TOTAL) issueB(gn);
                CP_COMMIT();                         // unconditional: keeps wait chain exact
                n++;
            }

            if (nkc == 16 || isL0x) __syncthreads(); // Hs reads done before rewrite
            if (l == 0 && t == 0) {                  // spill x-part gates
                const uint4* ap = (const uint4*)acc;
                uint4* gp = (uint4*)(Gx + (size_t)row0 * 512 + (size_t)tid * 64);
#pragma unroll
                for (int i = 0; i < 16; i++) gp[i] = ap[i];
            }

            // ---- cell epilogue: gates+c in regs, h -> Hs (STS) + Xout (STG) ----
#pragma unroll
            for (int mf = 0; mf < 4; mf++) {
                __half hv[4];
#pragma unroll
                for (int q = 0; q < 2; q++)
#pragma unroll
                    for (int d = 0; d < 2; d++) {
                        int cr = q * 2 + d;
                        int j  = w * 8 + t4 * 2 + d;
                        float gi = acc[mf][0][cr] + bs[j];
                        float gf = acc[mf][1][cr] + bs[128 + j];
                        float gg = acc[mf][2][cr] + bs[256 + j];
                        float go = acc[mf][3][cr] + bs[384 + j];
                        int ci = mf * 4 + q * 2 + d;
                        float cn = sigf(gf) * creg[ci] + sigf(gi) * tanh_fast(gg);
                        float h  = sigf(go) * tanh_fast(cn);
                        creg[ci] = cn;
                        hv[q * 2 + d] = __float2half_rn(h);
                    }
                int off = (w >> 1) * 1024 + mf * 256 + gidx * 8 + (w & 1) * 4;
                *(uint2*)&Hs[off] = *(const uint2*)hv;
                *(uint2*)&Xout[((size_t)t * BATCH + row0) * 128 + off] = *(const uint2*)hv;
            }

            if (t == TT - 1 && l + 1 < LAYERS) {
                __syncthreads();                     // bias reads done before rewrite
                bs[tid] = bih[(l + 1) * 512 + tid] + bhh[(l + 1) * 512 + tid];
#pragma unroll
                for (int i = 0; i < 16; i++) creg[i] = 0.f;
            }
            if (needX) xbuf ^= 1;
        }
        Xin  = Xout;
        Xout = (Xout == Xa) ? Xb : Xa;
    }
    CP_WAIT(0);
}

// ---------------- fc_out: packed-fp16 Y @ W^T + b, fused scatter ----------------
__global__ void __launch_bounds__(256) k_fcout(const __half* __restrict__ Y,
                                               const float* __restrict__ W,
                                               const float* __restrict__ bias,
                                               float* __restrict__ pred,
                                               float* __restrict__ plog) {
    __shared__ __align__(16) __half As[2048];
    __shared__ __align__(16) __half Bsm[80 * 16];
    const int tid  = threadIdx.x;
    const int lane = tid & 31;
    const int wm   = tid >> 5;
    const int row0 = blockIdx.x * 128;
    const int g    = lane >> 2;
    const int t4   = lane & 3;
    const int gidx = g * 4 + t4;

    float acc[10][4];
#pragma unroll
    for (int i = 0; i < 10; i++)
#pragma unroll
        for (int j = 0; j < 4; j++) acc[i][j] = 0.f;

    for (int kc = 0; kc < 8; kc++) {
        {
            int tilei = tid >> 7, rest = tid & 127;
            *(uint4*)&As[tid * 8] =
                *(const uint4*)&Y[(size_t)(row0 + tilei * 64) * 128 + kc * 1024 + rest * 8];
        }
#pragma unroll
        for (int i = 0; i < 5; i++) {
            int idx = tid + i * 256;
            int c = idx >> 4, kl = idx & 15;
            float v = (c < 75) ? W[(size_t)c * 128 + kc * 16 + kl] : 0.f;
            Bsm[c * 16 + kl] = __float2half_rn(v);
        }
        __syncthreads();
        uint4 Av = *(const uint4*)&As[(wm >> 2) * 1024 + (wm & 3) * 256 + gidx * 8];
#pragma unroll
        for (int nt = 0; nt < 10; nt++) {
            int col = nt * 8 + g;
            unsigned b0 = *(const unsigned*)&Bsm[col * 16 + t4 * 2];
            unsigned b1 = *(const unsigned*)&Bsm[col * 16 + 8 + t4 * 2];
            mma_f16(acc[nt], Av.x, Av.y, Av.z, Av.w, b0, b1);
        }
        __syncthreads();
    }
#pragma unroll
    for (int nt = 0; nt < 10; nt++)
#pragma unroll
        for (int cr = 0; cr < 4; cr++) {
            int col = nt * 8 + t4 * 2 + (cr & 1);
            if (col >= 75) continue;
            int r = row0 + wm * 16 + g + (cr >> 1) * 8;
            int t = r >> 13;
            int b = r & (BATCH - 1);
            float v = acc[nt][cr] + bias[col];
            if (col < 50) {
                int m = col >> 1, d = col & 1;
                pred[b * (NMODES * TT * 2) + m * (TT * 2) + t * 2 + d] = v;
            } else if (t == TT - 1) {
                plog[b * NMODES + (col - 50)] = v;
            }
        }
}

// ---------------- softmax over 25 modes ----------------
__global__ void __launch_bounds__(256) k_softmax(const float* __restrict__ plog,
                                                 float* __restrict__ out) {
    int b = blockIdx.x * blockDim.x + threadIdx.x;
    if (b >= BATCH) return;
    float v[NMODES];
    float m = -1e30f;
#pragma unroll
    for (int j = 0; j < NMODES; j++) {
        v[j] = plog[b * NMODES + j];
        m = fmaxf(m, v[j]);
    }
    float s = 0.f;
#pragma unroll
    for (int j = 0; j < NMODES; j++) {
        v[j] = __expf(v[j] - m);
        s += v[j];
    }
    float inv = __fdividef(1.f, s);
#pragma unroll
    for (int j = 0; j < NMODES; j++) out[b * NMODES + j] = v[j] * inv;
}

// ---------------- launcher ----------------
extern "C" void kernel_launch(void* const* d_in, const int* in_sizes, int n_in,
                              void* d_out, int out_size) {
    const float* backbone = (const float*)d_in[0];
    const float* fcW      = (const float*)d_in[1];
    const float* fcb      = (const float*)d_in[2];
    const float* Wih      = (const float*)d_in[3];
    const float* Whh      = (const float*)d_in[4];
    const float* bih      = (const float*)d_in[5];
    const float* bhh      = (const float*)d_in[6];
    const float* foW      = (const float*)d_in[7];
    const float* fob      = (const float*)d_in[8];

    float* out  = (float*)d_out;
    float* pred = out;
    float* prob = out + (size_t)BATCH * NMODES * TT * 2;

    __half *encp, *pXa, *pXb, *wp;
    float *plogb, *gxb;
    cudaGetSymbolAddress((void**)&encp,  g_encp);
    cudaGetSymbolAddress((void**)&pXa,   g_Xa);
    cudaGetSymbolAddress((void**)&pXb,   g_Xb);
    cudaGetSymbolAddress((void**)&wp,    g_Wp);
    cudaGetSymbolAddress((void**)&plogb, g_plog);
    cudaGetSymbolAddress((void**)&gxb,   g_Gx);

    cudaFuncSetAttribute(k_lstm, cudaFuncAttributeMaxDynamicSharedMemorySize, SMEM_BYTES);

    k_pack<<<(LAYERS * 16 * 16 * 512 + 255) / 256, 256>>>(Wih, Whh, wp);
    k_fcin<<<BATCH / 64, 256>>>(backbone, fcW, fcb, encp);
    k_lstm<<<BATCH / 64, 512, SMEM_BYTES>>>(encp, wp, bih, bhh, pXa, pXb, gxb);
    // LAYERS = 10 (even): final output lives in g_Xb
    k_fcout<<<(TT * BATCH) / 128, 256>>>(pXb, foW, fob, pred, plogb);
    k_softmax<<<BATCH / 256, 256>>>(plogb, prob);
}